// round 2
// baseline (speedup 1.0000x reference)
#include <cuda_runtime.h>
#include <cstdint>

#define BB 8
#define LL 256
#define DD 256
#define CC 32

// 8*256*256*32 floats = 64Mi floats = 256MB? no: 16,777,216 floats = 67MB
__device__ float g_h[(size_t)BB * LL * LL * CC];

// ---- packed f32x2 helpers (Blackwell FFMA2) ----
__device__ __forceinline__ unsigned long long ffma2(unsigned long long a,
                                                    unsigned long long b,
                                                    unsigned long long c) {
    unsigned long long d;
    asm("fma.rn.f32x2 %0, %1, %2, %3;" : "=l"(d) : "l"(a), "l"(b), "l"(c));
    return d;
}
__device__ __forceinline__ unsigned long long pack2(float x) {
    unsigned long long r;
    unsigned int u = __float_as_uint(x);
    asm("mov.b64 %0, {%1, %1};" : "=l"(r) : "r"(u));
    return r;
}

// ============================================================
// Kernel 1: pairwise features + 1x1 conv (channel GEMM) + relu + mask
// block = (i, b); 256 threads, thread = j. 8.6 G FMA total.
// ============================================================
__global__ void __launch_bounds__(256) pair_gemm_kernel(
    const float* __restrict__ x,      // [B, L, D]
    const int*   __restrict__ plen,   // [B]
    const float* __restrict__ W1,     // [2D, C]
    const float* __restrict__ b1)     // [C]
{
    const int i   = blockIdx.x;
    const int b   = blockIdx.y;
    const int tid = threadIdx.x;
    const int j   = tid;
    const int len = __ldg(&plen[b]);

    float* hout = g_h + (((size_t)b * LL + i) * LL) * CC;

    if (i >= len) {
        // whole row masked: write zeros, uniform early exit (no later barriers)
        float4 z4 = make_float4(0.f, 0.f, 0.f, 0.f);
        float4* o = reinterpret_cast<float4*>(hout + (size_t)j * CC);
#pragma unroll
        for (int k = 0; k < 8; k++) o[k] = z4;
        return;
    }

    __shared__ __align__(16) float sXi[DD];
    __shared__ __align__(16) float sXJ[LL * 33];   // padded stride 33: conflict-free
    __shared__ __align__(16) float sWa[32 * CC];   // W1 mul-half chunk   [32 d][32 c]
    __shared__ __align__(16) float sWb[32 * CC];   // W1 sub-half chunk

    // xi row (broadcast source)
    sXi[tid] = x[((size_t)b * LL + i) * DD + tid];

    const bool active = (j < len);
    const float* xb = x + (size_t)b * LL * DD;

    unsigned long long acc[16];   // 32 channels as 16 packed f32x2
#pragma unroll
    for (int k = 0; k < 16; k++) acc[k] = 0ULL;

    for (int d0 = 0; d0 < DD; d0 += 32) {
        __syncthreads();
        // stage x[b, all j, d0..d0+31] : warp-coalesced global, conflict-free shared
#pragma unroll
        for (int k = 0; k < 32; k++) {
            int idx = tid + k * 256;
            int jj = idx >> 5;
            int dd = idx & 31;
            sXJ[jj * 33 + dd] = xb[(size_t)jj * DD + d0 + dd];
        }
        // stage W1 chunks (mul rows d0.., sub rows 256+d0..)
#pragma unroll
        for (int k = 0; k < 4; k++) {
            int idx = tid + k * 256;                  // 1024 elems each
            sWa[idx] = W1[(size_t)d0 * CC + idx];
            sWb[idx] = W1[((size_t)DD + d0) * CC + idx];
        }
        __syncthreads();

        if (active) {
#pragma unroll
            for (int dd = 0; dd < 32; dd++) {
                float xi = sXi[d0 + dd];
                float xj = sXJ[tid * 33 + dd];
                unsigned long long m2 = pack2(xi * xj);
                unsigned long long s2 = pack2(fabsf(xi - xj));
                const ulonglong2* wa = reinterpret_cast<const ulonglong2*>(sWa + dd * CC);
                const ulonglong2* wb = reinterpret_cast<const ulonglong2*>(sWb + dd * CC);
#pragma unroll
                for (int k = 0; k < 8; k++) {
                    ulonglong2 a  = wa[k];
                    ulonglong2 bv = wb[k];
                    acc[2 * k]     = ffma2(m2, a.x,  acc[2 * k]);
                    acc[2 * k + 1] = ffma2(m2, a.y,  acc[2 * k + 1]);
                    acc[2 * k]     = ffma2(s2, bv.x, acc[2 * k]);
                    acc[2 * k + 1] = ffma2(s2, bv.y, acc[2 * k + 1]);
                }
            }
        }
    }

    // epilogue: + b1, relu, mask, store
    float outv[32];
    if (active) {
#pragma unroll
        for (int k = 0; k < 16; k++) {
            float2 f2 = *reinterpret_cast<float2*>(&acc[k]);
            outv[2 * k]     = fmaxf(f2.x + __ldg(&b1[2 * k]), 0.f);
            outv[2 * k + 1] = fmaxf(f2.y + __ldg(&b1[2 * k + 1]), 0.f);
        }
    } else {
#pragma unroll
        for (int k = 0; k < 32; k++) outv[k] = 0.f;
    }
    float4* o = reinterpret_cast<float4*>(hout + (size_t)j * CC);
#pragma unroll
    for (int k = 0; k < 8; k++)
        o[k] = make_float4(outv[4 * k], outv[4 * k + 1], outv[4 * k + 2], outv[4 * k + 3]);
}

// ============================================================
// Kernel 2: 7x7 conv (C=32 -> 1), SAME padding, +b2, output mask.
// warp = one (b,i,j0..j0+3) group; lane = channel. 0.82 G FMA.
// h loads are lane-coalesced 128B; window reuse over 4 j-outputs.
// ============================================================
__global__ void __launch_bounds__(256) conv7x7_kernel(
    const float* __restrict__ W2,   // [7,7,32,1] HWIO
    const float* __restrict__ b2v,  // [1]
    const int*   __restrict__ plen, // [B]
    float*       __restrict__ out)  // [B, L, L, 1]
{
    __shared__ float sW[7 * 7 * CC];
    for (int idx = threadIdx.x; idx < 7 * 7 * CC; idx += 256) sW[idx] = W2[idx];
    __syncthreads();

    const int warp = threadIdx.x >> 5;
    const int lane = threadIdx.x & 31;
    const int task = blockIdx.x * 8 + warp;          // 131072 tasks
    const int b    = task >> 14;                     // / (256*64)
    const int rem  = task & 16383;
    const int i    = rem >> 6;
    const int j0   = (rem & 63) << 2;
    const int len  = __ldg(&plen[b]);

    float a0 = 0.f, a1 = 0.f, a2 = 0.f, a3 = 0.f;

#pragma unroll
    for (int di = 0; di < 7; di++) {
        int r = i + di - 3;
        if (r < 0 || r >= LL) continue;
        const float* hrow = g_h + (((size_t)b * LL + r) * LL) * CC + lane;
        float hv[10];
#pragma unroll
        for (int k = 0; k < 10; k++) {
            int col = j0 - 3 + k;
            hv[k] = (col >= 0 && col < LL) ? hrow[(size_t)col * CC] : 0.f;
        }
#pragma unroll
        for (int dj = 0; dj < 7; dj++) {
            float wv = sW[(di * 7 + dj) * CC + lane];
            a0 = fmaf(hv[dj],     wv, a0);
            a1 = fmaf(hv[dj + 1], wv, a1);
            a2 = fmaf(hv[dj + 2], wv, a2);
            a3 = fmaf(hv[dj + 3], wv, a3);
        }
    }

    // reduce over channels (lanes)
#pragma unroll
    for (int off = 16; off; off >>= 1) {
        a0 += __shfl_xor_sync(0xffffffffu, a0, off);
        a1 += __shfl_xor_sync(0xffffffffu, a1, off);
        a2 += __shfl_xor_sync(0xffffffffu, a2, off);
        a3 += __shfl_xor_sync(0xffffffffu, a3, off);
    }

    if (lane < 4) {
        float v = (lane == 0) ? a0 : (lane == 1) ? a1 : (lane == 2) ? a2 : a3;
        int j = j0 + lane;
        float res = (i < len && j < len) ? (v + __ldg(b2v)) : 0.f;
        out[((size_t)b * LL + i) * LL + j] = res;
    }
}

// ============================================================
extern "C" void kernel_launch(void* const* d_in, const int* in_sizes, int n_in,
                              void* d_out, int out_size) {
    const float* x    = (const float*)d_in[0];   // encoder_output [8,256,256]
    const int*   plen = (const int*)  d_in[1];   // protein_length [8]
    const float* W1   = (const float*)d_in[2];   // [512,32]
    const float* b1   = (const float*)d_in[3];   // [32]
    const float* W2   = (const float*)d_in[4];   // [7,7,32,1]
    const float* b2   = (const float*)d_in[5];   // [1]
    float* out = (float*)d_out;                  // [8,256,256,1]

    dim3 g1(LL, BB);
    pair_gemm_kernel<<<g1, 256>>>(x, plen, W1, b1);
    conv7x7_kernel<<<16384, 256>>>(W2, b2, plen, out);
}